// round 8
// baseline (speedup 1.0000x reference)
#include <cuda_runtime.h>
#include <cstdint>

// ============================================================================
// out = BN(scale * (x @ W^T)) -- int8 two-word quantized GEMM (legacy IMMA).
//   x ~= alphaA[m]*(X1 + X2/128),  w ~= alphaB[n]*(W1 + W2/128)
//   x.w ~= aA*aB*( S11 + (S12 + S21)/128 ),  S via mma.m16n8k32.s8 (s32 exact)
// rel err ~1e-4. Phase 1: per-row quantize. Phase 2: GEMM 128x128 CTA tiles,
// 512 thr, warp tile 64x16, K-chunk 64 int8, 4-stage cp.async pipeline.
// ============================================================================

#define B_DIM   4096
#define IN_DIM  2048
#define OUT_DIM 2048
#define KP      4096              // packed bytes per row: [X1(2048) | X2(2048)]
#define EPSV    1e-5f

#define TM 128
#define TN 128
#define THREADS 512
#define NCHT 96                   // 3 terms * (2048/64) chunks, K-chunk = 64 int8

#define ROWB 80                   // padded smem row: 64B data + 16B (conflict-free)
#define SA_BYTES (128 * ROWB)     // 10240
#define SB_BYTES (128 * ROWB)     // 10240
#define STAGE_SZ (SA_BYTES + SB_BYTES)       // 20480
#define OFF_CA 0
#define OFF_CB 512
#define OFF_AL 1024
#define OFF_ST 2048
#define SMEM_BYTES (OFF_ST + 4 * STAGE_SZ)   // 83968

// int8 scratch: [row][X1(2048) | X2(2048)]
__device__ __align__(16) int8_t g_A[(size_t)B_DIM * KP];     // 16 MB
__device__ __align__(16) int8_t g_B[(size_t)OUT_DIM * KP];   // 8 MB
__device__ float g_alA[B_DIM];
__device__ float g_alB[OUT_DIM];

// ---------------------------------------------------------------- helpers
static __device__ __forceinline__ uint32_t smem_u32(const void* p) {
    uint32_t a;
    asm("{ .reg .u64 t; cvta.to.shared.u64 t, %1; cvt.u32.u64 %0, t; }" : "=r"(a) : "l"(p));
    return a;
}

#define CP_ASYNC16(dst, src) \
    asm volatile("cp.async.cg.shared.global [%0], [%1], 16;" :: "r"(dst), "l"(src))
#define CP_COMMIT() asm volatile("cp.async.commit_group;" ::: "memory")
#define CP_WAIT2()  asm volatile("cp.async.wait_group 2;" ::: "memory")

#define LDSM4(r, addr) \
    asm volatile("ldmatrix.sync.aligned.m8n8.x4.shared.b16 {%0,%1,%2,%3}, [%4];" \
                 : "=r"((r)[0]), "=r"((r)[1]), "=r"((r)[2]), "=r"((r)[3]) : "r"(addr))

#define IMMA(d, a, b0, b1) \
    asm volatile("mma.sync.aligned.m16n8k32.row.col.s32.s8.s8.s32 " \
                 "{%0,%1,%2,%3}, {%4,%5,%6,%7}, {%8,%9}, {%0,%1,%2,%3};" \
                 : "+r"((d)[0]), "+r"((d)[1]), "+r"((d)[2]), "+r"((d)[3]) \
                 : "r"((a)[0]), "r"((a)[1]), "r"((a)[2]), "r"((a)[3]), \
                   "r"(b0), "r"(b1))

static __device__ __forceinline__ uint32_t pack4(int q0, int q1, int q2, int q3) {
    return (uint32_t)(q0 & 255) | ((uint32_t)(q1 & 255) << 8) |
           ((uint32_t)(q2 & 255) << 16) | ((uint32_t)q3 << 24);
}

// ---------------------------------------------------------------- quantize
// One block per row: amax -> alpha, then X1 = rint(x/a), X2 = rint(128*(x/a-X1))
__global__ __launch_bounds__(256) void quant_kernel(
    const float* __restrict__ src, int8_t* __restrict__ dst,
    float* __restrict__ alpha) {
    const int row = blockIdx.x, t = threadIdx.x;
    const float* s = src + (size_t)row * IN_DIM + t * 8;
    float4 v0 = *reinterpret_cast<const float4*>(s);
    float4 v1 = *reinterpret_cast<const float4*>(s + 4);

    float m = fmaxf(fmaxf(fmaxf(fabsf(v0.x), fabsf(v0.y)), fmaxf(fabsf(v0.z), fabsf(v0.w))),
                    fmaxf(fmaxf(fabsf(v1.x), fabsf(v1.y)), fmaxf(fabsf(v1.z), fabsf(v1.w))));
#pragma unroll
    for (int o = 16; o; o >>= 1) m = fmaxf(m, __shfl_xor_sync(0xFFFFFFFFu, m, o));
    __shared__ float red[8];
    __shared__ float s_alpha;
    if ((t & 31) == 0) red[t >> 5] = m;
    __syncthreads();
    if (t == 0) {
        float mm = red[0];
#pragma unroll
        for (int i = 1; i < 8; i++) mm = fmaxf(mm, red[i]);
        s_alpha = fmaxf(mm, 1e-20f) * (1.0f / 127.4f);
        alpha[row] = s_alpha;
    }
    __syncthreads();
    const float inv = 1.0f / s_alpha;

    float f[8] = {v0.x, v0.y, v0.z, v0.w, v1.x, v1.y, v1.z, v1.w};
    int q1[8], q2[8];
#pragma unroll
    for (int i = 0; i < 8; i++) {
        float u = f[i] * inv;
        q1[i] = __float2int_rn(u);                       // |u| <= 127.4 -> [-127,127]
        q2[i] = __float2int_rn((u - (float)q1[i]) * 128.0f);   // [-64,64]
    }
    uint2 w1 = make_uint2(pack4(q1[0], q1[1], q1[2], q1[3]), pack4(q1[4], q1[5], q1[6], q1[7]));
    uint2 w2 = make_uint2(pack4(q2[0], q2[1], q2[2], q2[3]), pack4(q2[4], q2[5], q2[6], q2[7]));
    *reinterpret_cast<uint2*>(dst + (size_t)row * KP + t * 8) = w1;
    *reinterpret_cast<uint2*>(dst + (size_t)row * KP + 2048 + t * 8) = w2;
}

// ---------------------------------------------------------------- GEMM kernel
__global__ __launch_bounds__(THREADS, 1) void gemm_bn_kernel(
    const float* __restrict__ scale, const float* __restrict__ mean,
    const float* __restrict__ var, const float* __restrict__ gamma,
    const float* __restrict__ beta, float* __restrict__ out) {
    extern __shared__ __align__(16) char smem[];
    const uint32_t sb = smem_u32(smem);
    const int tid = threadIdx.x, wid = tid >> 5, lane = tid & 31;
    const int warp_m = wid & 1;        // 2 warps over M (64 rows each)
    const int warp_n = wid >> 1;       // 8 warps over N (16 cols each)
    const int rowg = blockIdx.x * TM;
    const int colg = blockIdx.y * TN;

    // BN+scale coefficients folded with alphaB: out = accf*alA[r]*As[c] + Bs[c]
    if (tid < TN) {
        int cg = colg + tid;
        float ga = gamma[cg], inv = rsqrtf(var[cg] + EPSV);
        reinterpret_cast<float*>(smem + OFF_CA)[tid] = ga * scale[cg] * inv * g_alB[cg];
        reinterpret_cast<float*>(smem + OFF_CB)[tid] = beta[cg] - ga * mean[cg] * inv;
    } else if (tid < TN + TM) {
        reinterpret_cast<float*>(smem + OFF_AL)[tid - TN] = g_alA[rowg + tid - TN];
    }

    int accm[4][2][4], accc[4][2][4];
#pragma unroll
    for (int mt = 0; mt < 4; mt++)
#pragma unroll
        for (int ng = 0; ng < 2; ng++)
#pragma unroll
            for (int e = 0; e < 4; e++) { accm[mt][ng][e] = 0; accc[mt][ng][e] = 0; }

    // chunk ch in [0,96): term = ch/32 (0: X1W1->main, 1: X1W2->corr, 2: X2W1->corr)
    auto issue = [&](int ch, int st) {
        int t = ch >> 5, kk = (ch & 31) * 64;
        const int8_t* asrc = g_A + (size_t)rowg * KP + ((t == 2) ? 2048 : 0) + kk;
        const int8_t* bsrc = g_B + (size_t)colg * KP + ((t == 1) ? 2048 : 0) + kk;
        uint32_t abase = sb + OFF_ST + st * STAGE_SZ;
        uint32_t bbase = abase + SA_BYTES;
        int row = tid >> 2, seg = tid & 3;
        CP_ASYNC16(abase + row * ROWB + seg * 16, asrc + (size_t)row * KP + seg * 16);
        CP_ASYNC16(bbase + row * ROWB + seg * 16, bsrc + (size_t)row * KP + seg * 16);
        CP_COMMIT();
    };

    issue(0, 0); issue(1, 1); issue(2, 2);

#pragma unroll 1
    for (int u = 0; u < NCHT; u++) {
        CP_WAIT2();
        __syncthreads();
        int nc = u + 3;
        issue(nc < NCHT ? nc : 0, nc & 3);

        const int trm = u >> 5;
        uint32_t abase = sb + OFF_ST + (u & 3) * STAGE_SZ;
        uint32_t bbase = abase + SA_BYTES;
#pragma unroll
        for (int ks = 0; ks < 2; ks++) {
            int kb = ks * 32 + (lane >> 4) * 16;
            uint32_t a[4][4], b[4];
#pragma unroll
            for (int mt = 0; mt < 4; mt++)
                LDSM4(a[mt], abase + (warp_m * 64 + mt * 16 + (lane & 15)) * ROWB + kb);
            LDSM4(b, bbase + (warp_n * 16 + (lane & 15)) * ROWB + kb);
            if (trm == 0) {
#pragma unroll
                for (int mt = 0; mt < 4; mt++) {
                    IMMA(accm[mt][0], a[mt], b[0], b[2]);
                    IMMA(accm[mt][1], a[mt], b[1], b[3]);
                }
            } else {
#pragma unroll
                for (int mt = 0; mt < 4; mt++) {
                    IMMA(accc[mt][0], a[mt], b[0], b[2]);
                    IMMA(accc[mt][1], a[mt], b[1], b[3]);
                }
            }
        }
    }
    asm volatile("cp.async.wait_group 0;" ::: "memory");

    // ---- epilogue ----
    const float* As = reinterpret_cast<const float*>(smem + OFF_CA);
    const float* Bs = reinterpret_cast<const float*>(smem + OFF_CB);
    const float* Al = reinterpret_cast<const float*>(smem + OFF_AL);
    const int r0 = lane >> 2, c0 = (lane & 3) * 2;
#pragma unroll
    for (int mt = 0; mt < 4; mt++) {
        int lr = warp_m * 64 + mt * 16 + r0;
        float aA0 = Al[lr], aA1 = Al[lr + 8];
#pragma unroll
        for (int ng = 0; ng < 2; ng++) {
            int lc = warp_n * 16 + ng * 8 + c0;
            float a0 = As[lc], a1 = As[lc + 1];
            float b0 = Bs[lc], b1 = Bs[lc + 1];
            float f0 = __int2float_rn(accm[mt][ng][0]) + __int2float_rn(accc[mt][ng][0]) * 0.0078125f;
            float f1 = __int2float_rn(accm[mt][ng][1]) + __int2float_rn(accc[mt][ng][1]) * 0.0078125f;
            float f2 = __int2float_rn(accm[mt][ng][2]) + __int2float_rn(accc[mt][ng][2]) * 0.0078125f;
            float f3 = __int2float_rn(accm[mt][ng][3]) + __int2float_rn(accc[mt][ng][3]) * 0.0078125f;
            float2 v0 = make_float2(f0 * aA0 * a0 + b0, f1 * aA0 * a1 + b1);
            float2 v1 = make_float2(f2 * aA1 * a0 + b0, f3 * aA1 * a1 + b1);
            *reinterpret_cast<float2*>(out + (size_t)(rowg + lr) * OUT_DIM + colg + lc) = v0;
            *reinterpret_cast<float2*>(out + (size_t)(rowg + lr + 8) * OUT_DIM + colg + lc) = v1;
        }
    }
}

// ---------------------------------------------------------------- launch
extern "C" void kernel_launch(void* const* d_in, const int* in_sizes, int n_in,
                              void* d_out, int out_size) {
    const float* x     = (const float*)d_in[0];
    const float* w     = (const float*)d_in[1];
    const float* scale = (const float*)d_in[2];
    const float* mean  = (const float*)d_in[3];
    const float* var   = (const float*)d_in[4];
    const float* gamma = (const float*)d_in[5];
    const float* beta  = (const float*)d_in[6];
    float* out = (float*)d_out;

    cudaFuncSetAttribute(gemm_bn_kernel,
                         cudaFuncAttributeMaxDynamicSharedMemorySize, SMEM_BYTES);

    int8_t *dA = nullptr, *dB = nullptr;
    float *aA = nullptr, *aB = nullptr;
    cudaGetSymbolAddress((void**)&dA, g_A);
    cudaGetSymbolAddress((void**)&dB, g_B);
    cudaGetSymbolAddress((void**)&aA, g_alA);
    cudaGetSymbolAddress((void**)&aB, g_alB);

    quant_kernel<<<B_DIM, 256>>>(x, dA, aA);
    quant_kernel<<<OUT_DIM, 256>>>(w, dB, aB);

    dim3 grid(B_DIM / TM, OUT_DIM / TN);   // 32 x 16 = 512 CTAs
    gemm_bn_kernel<<<grid, THREADS, SMEM_BYTES>>>(scale, mean, var, gamma, beta, out);
}

// round 10
// speedup vs baseline: 6.1934x; 6.1934x over previous
#include <cuda_runtime.h>
#include <cuda_fp16.h>
#include <cstdint>

// ============================================================================
// out = BN(scale * (x @ W^T)) -- single-term fp16 GEMM on legacy HMMA.
//   fp16 RN quantization, fp32 accumulate: norm rel err ~4e-4 (<1e-3 gate).
// Phase 1: fp32 -> fp16 convert. Phase 2: GEMM 128x256 CTA tiles, 512 thr,
// warp tile 64x32, K-chunk 64 fp16 (128B rows), 4-stage cp.async pipeline.
// ============================================================================

#define B_DIM   4096
#define IN_DIM  2048
#define OUT_DIM 2048
#define EPSV    1e-5f

#define TM 128
#define TN 256
#define THREADS 512
#define NCHT 32                   // 2048 / 64

#define ROWB 144                  // 128B data + 16B pad (ldmatrix conflict-free)
#define SA_BYTES (128 * ROWB)     // 18432
#define SB_BYTES (256 * ROWB)     // 36864
#define STAGE_SZ (SA_BYTES + SB_BYTES)       // 55296
#define OFF_CA 0
#define OFF_CB 1024
#define OFF_ST 2048
#define SMEM_BYTES (OFF_ST + 4 * STAGE_SZ)   // 223232

// fp16 scratch
__device__ __align__(16) __half g_hA[(size_t)B_DIM * IN_DIM];     // 16 MB
__device__ __align__(16) __half g_hB[(size_t)OUT_DIM * IN_DIM];   // 8 MB

// ---------------------------------------------------------------- helpers
static __device__ __forceinline__ uint32_t smem_u32(const void* p) {
    uint32_t a;
    asm("{ .reg .u64 t; cvta.to.shared.u64 t, %1; cvt.u32.u64 %0, t; }" : "=r"(a) : "l"(p));
    return a;
}

#define CP_ASYNC16(dst, src) \
    asm volatile("cp.async.cg.shared.global [%0], [%1], 16;" :: "r"(dst), "l"(src))
#define CP_COMMIT() asm volatile("cp.async.commit_group;" ::: "memory")
#define CP_WAIT2()  asm volatile("cp.async.wait_group 2;" ::: "memory")

#define LDSM4(r, addr) \
    asm volatile("ldmatrix.sync.aligned.m8n8.x4.shared.b16 {%0,%1,%2,%3}, [%4];" \
                 : "=r"((r)[0]), "=r"((r)[1]), "=r"((r)[2]), "=r"((r)[3]) : "r"(addr))

#define MMA16816(d, a, b0, b1) \
    asm volatile("mma.sync.aligned.m16n8k16.row.col.f32.f16.f16.f32 " \
                 "{%0,%1,%2,%3}, {%4,%5,%6,%7}, {%8,%9}, {%0,%1,%2,%3};" \
                 : "+f"((d)[0]), "+f"((d)[1]), "+f"((d)[2]), "+f"((d)[3]) \
                 : "r"((a)[0]), "r"((a)[1]), "r"((a)[2]), "r"((a)[3]), \
                   "r"(b0), "r"(b1))

// ---------------------------------------------------------------- convert
__global__ __launch_bounds__(256) void cvt_half_kernel(
    const float* __restrict__ src, __half* __restrict__ dst, int total) {
    int64_t i = ((int64_t)blockIdx.x * 256 + threadIdx.x) * 8;
    if (i >= total) return;
    float4 v0 = *reinterpret_cast<const float4*>(src + i);
    float4 v1 = *reinterpret_cast<const float4*>(src + i + 4);
    __half2 h0 = __float22half2_rn(make_float2(v0.x, v0.y));
    __half2 h1 = __float22half2_rn(make_float2(v0.z, v0.w));
    __half2 h2 = __float22half2_rn(make_float2(v1.x, v1.y));
    __half2 h3 = __float22half2_rn(make_float2(v1.z, v1.w));
    uint4 o;
    o.x = *reinterpret_cast<uint32_t*>(&h0);
    o.y = *reinterpret_cast<uint32_t*>(&h1);
    o.z = *reinterpret_cast<uint32_t*>(&h2);
    o.w = *reinterpret_cast<uint32_t*>(&h3);
    *reinterpret_cast<uint4*>(dst + i) = o;
}

// ---------------------------------------------------------------- GEMM kernel
__global__ __launch_bounds__(THREADS, 1) void gemm_bn_kernel(
    const float* __restrict__ scale, const float* __restrict__ mean,
    const float* __restrict__ var, const float* __restrict__ gamma,
    const float* __restrict__ beta, float* __restrict__ out) {
    extern __shared__ __align__(16) char smem[];
    const uint32_t sb = smem_u32(smem);
    const int tid = threadIdx.x, wid = tid >> 5, lane = tid & 31;
    const int warp_m = wid & 1;        // 2 warps over M (64 rows each)
    const int warp_n = wid >> 1;       // 8 warps over N (32 cols each)
    const int rowg = blockIdx.x * TM;
    const int colg = blockIdx.y * TN;

    // BN coefficients: out = acc * As[col] + Bs[col]
    if (tid < TN) {
        int cg = colg + tid;
        float ga = gamma[cg], inv = rsqrtf(var[cg] + EPSV);
        reinterpret_cast<float*>(smem + OFF_CA)[tid] = ga * scale[cg] * inv;
        reinterpret_cast<float*>(smem + OFF_CB)[tid] = beta[cg] - ga * mean[cg] * inv;
    }

    float acc[4][4][4];
#pragma unroll
    for (int mt = 0; mt < 4; mt++)
#pragma unroll
        for (int nt = 0; nt < 4; nt++)
#pragma unroll
            for (int e = 0; e < 4; e++) acc[mt][nt][e] = 0.0f;

    // chunk ch in [0,32): K-offset = ch*64
    auto issue = [&](int ch, int st) {
        int kk = ch * 64;
        const __half* asrc = g_hA + (size_t)rowg * IN_DIM + kk;
        const __half* bsrc = g_hB + (size_t)colg * IN_DIM + kk;
        uint32_t abase = sb + OFF_ST + st * STAGE_SZ;
        uint32_t bbase = abase + SA_BYTES;
#pragma unroll
        for (int j = 0; j < 2; j++) {   // A: 128 rows x 8 x 16B
            int idx = tid + j * THREADS;
            int row = idx >> 3, seg = idx & 7;
            CP_ASYNC16(abase + row * ROWB + seg * 16, asrc + (size_t)row * IN_DIM + seg * 8);
        }
#pragma unroll
        for (int j = 0; j < 4; j++) {   // B: 256 rows x 8 x 16B
            int idx = tid + j * THREADS;
            int row = idx >> 3, seg = idx & 7;
            CP_ASYNC16(bbase + row * ROWB + seg * 16, bsrc + (size_t)row * IN_DIM + seg * 8);
        }
        CP_COMMIT();
    };

    issue(0, 0); issue(1, 1); issue(2, 2);

#pragma unroll 1
    for (int u = 0; u < NCHT; u++) {
        CP_WAIT2();                 // group u complete
        __syncthreads();
        int nc = u + 3;
        issue(nc < NCHT ? nc : 0, nc & 3);   // tail: dummy refill, never consumed

        uint32_t abase = sb + OFF_ST + (u & 3) * STAGE_SZ;
        uint32_t bbase = abase + SA_BYTES;
#pragma unroll
        for (int ks = 0; ks < 4; ks++) {
            int kb = ks * 32 + (lane >> 4) * 16;
            uint32_t a[4][4], b[2][4];
#pragma unroll
            for (int mt = 0; mt < 4; mt++)
                LDSM4(a[mt], abase + (warp_m * 64 + mt * 16 + (lane & 15)) * ROWB + kb);
#pragma unroll
            for (int np = 0; np < 2; np++)
                LDSM4(b[np], bbase + (warp_n * 32 + np * 16 + (lane & 15)) * ROWB + kb);
#pragma unroll
            for (int mt = 0; mt < 4; mt++)
#pragma unroll
                for (int nt = 0; nt < 4; nt++)
                    MMA16816(acc[mt][nt], a[mt],
                             b[nt >> 1][nt & 1], b[nt >> 1][2 + (nt & 1)]);
        }
    }
    asm volatile("cp.async.wait_group 0;" ::: "memory");

    // ---- epilogue: BN apply from registers, direct store ----
    const float* As = reinterpret_cast<const float*>(smem + OFF_CA);
    const float* Bs = reinterpret_cast<const float*>(smem + OFF_CB);
    const int r0 = lane >> 2, c0 = (lane & 3) * 2;
#pragma unroll
    for (int mt = 0; mt < 4; mt++) {
        int gr = rowg + warp_m * 64 + mt * 16 + r0;
#pragma unroll
        for (int nt = 0; nt < 4; nt++) {
            int lc = warp_n * 32 + nt * 8 + c0;
            float a0 = As[lc], a1 = As[lc + 1];
            float b0 = Bs[lc], b1 = Bs[lc + 1];
            float2 v0 = make_float2(acc[mt][nt][0] * a0 + b0, acc[mt][nt][1] * a1 + b1);
            float2 v1 = make_float2(acc[mt][nt][2] * a0 + b0, acc[mt][nt][3] * a1 + b1);
            *reinterpret_cast<float2*>(out + (size_t)gr * OUT_DIM + colg + lc) = v0;
            *reinterpret_cast<float2*>(out + (size_t)(gr + 8) * OUT_DIM + colg + lc) = v1;
        }
    }
}

// ---------------------------------------------------------------- launch
extern "C" void kernel_launch(void* const* d_in, const int* in_sizes, int n_in,
                              void* d_out, int out_size) {
    const float* x     = (const float*)d_in[0];
    const float* w     = (const float*)d_in[1];
    const float* scale = (const float*)d_in[2];
    const float* mean  = (const float*)d_in[3];
    const float* var   = (const float*)d_in[4];
    const float* gamma = (const float*)d_in[5];
    const float* beta  = (const float*)d_in[6];
    float* out = (float*)d_out;

    cudaFuncSetAttribute(gemm_bn_kernel,
                         cudaFuncAttributeMaxDynamicSharedMemorySize, SMEM_BYTES);

    __half *hA = nullptr, *hB = nullptr;
    cudaGetSymbolAddress((void**)&hA, g_hA);
    cudaGetSymbolAddress((void**)&hB, g_hB);

    int total_x = B_DIM * IN_DIM;          // 8388608
    int total_w = OUT_DIM * IN_DIM;        // 4194304
    cvt_half_kernel<<<total_x / (256 * 8), 256>>>(x, hA, total_x);
    cvt_half_kernel<<<total_w / (256 * 8), 256>>>(w, hB, total_w);

    dim3 grid(B_DIM / TM, OUT_DIM / TN);   // 32 x 8 = 256 CTAs
    gemm_bn_kernel<<<grid, THREADS, SMEM_BYTES>>>(scale, mean, var, gamma, beta, out);
}